// round 8
// baseline (speedup 1.0000x reference)
#include <cuda_runtime.h>
#include <cstdint>

// LambdaLoss: B=4096 lists, L=128 items.
// loss = mean over valid lists of
//        [ sum_{i,j: rel_i>rel_j} (rel_i-rel_j)*softplus(-(p_i-p_j)) / cnt ]
//
// Factorized: softplus(-(p_w-p_l)) = ln(1 + e^{p_l}*e^{-p_w}); precompute
// e_i = exp(p_i), rec_i = exp(-p_i) -> one lg2 per pair.
// Counting-sort by rel: winner = higher sorted index -> |rd| is always the
// right weight; orientation picks the multiplicand.
//
// R8 (smem-bandwidth fix): pair table T (float2 = 8 B/pair, was 16):
//   T[i]     = (rec_i, rel_i)   i in [0,128)   -- used by non-wrap pairs
//   T[128+i] = (e_i,  rel_i)    i in [0,64)    -- used by wrapped pairs
// Ring partner index j+k hits the right section AUTOMATICALLY:
//   j+k <  128 -> rec-section, t = eS  * rec_p
//   j+k >= 128 -> e-section of partner (j+k-128), t = rcS * e_p
// so the only select is the self factor m = (j+k<128) ? eS : rcS.
// 128 threads/list; k=1..63 covers ring distances 1..63 once; threads j<64
// do the distance-64 pair. 128*63 + 64 = 8128 = C(128,2).

#define LL_B   4096
#define LL_L   128
#define LOG2E  1.4426950408889634f
#define LN2    0.6931471805599453f

__device__ float g_sum   = 0.0f;
__device__ int   g_valid = 0;
__device__ int   g_done  = 0;

__device__ __forceinline__ float fast_ex2(float x) {
    float r; asm("ex2.approx.f32 %0, %1;" : "=f"(r) : "f"(x)); return r;
}
__device__ __forceinline__ float fast_lg2(float x) {
    float r; asm("lg2.approx.f32 %0, %1;" : "=f"(r) : "f"(x)); return r;
}

__global__ __launch_bounds__(128) void ll_main_kernel(
    const float* __restrict__ pred,
    const float* __restrict__ rel,
    float* __restrict__ out)
{
    __shared__ float2 T[192];   // [0,128): (rec,rel); [128,192): (e,rel)
    __shared__ float  E[128];   // e by sorted index (for self factor)
    __shared__ int    hist[8];
    __shared__ int    base[8];
    __shared__ float  wsum[4];

    const int j    = threadIdx.x;
    const int list = blockIdx.x;

    const float p = pred[list * LL_L + j];
    const float r = rel [list * LL_L + j];
    const int   c = (int)r;            // rel in {0..4}

    // exp work is sort-independent — overlaps the histogram barriers
    const float q  = p * LOG2E;
    const float e  = fast_ex2(q);
    const float rc = fast_ex2(-q);

    if (j < 8) hist[j] = 0;
    __syncthreads();
    atomicAdd(&hist[c], 1);
    __syncthreads();
    if (j == 0) {
        int a = 0;
#pragma unroll
        for (int cc = 0; cc < 5; cc++) { base[cc] = a; a += hist[cc]; }
    }
    __syncthreads();

    // rank + scatter
    const int pos = atomicAdd(&base[c], 1);
    T[pos] = make_float2(rc, r);
    E[pos] = e;
    if (pos < 64) T[128 + pos] = make_float2(e, r);
    __syncthreads();

    // self values at sorted position j
    const float2 selfT = T[j];
    const float rcS = selfT.x, rS = selfT.y;
    const float eS  = E[j];

    float acc0 = 0.0f, acc1 = 0.0f, acc2 = 0.0f, acc3 = 0.0f;

    // one LDS.64 per pair; m select is index-derived (j+K vs 128)
#define LL_PAIR(K, ACC)                                                   \
    {                                                                     \
        const float2 v = T[j + (K)];                                      \
        const float  m = ((j + (K)) < LL_L) ? eS : rcS;                   \
        const float rd = v.y - rS;                                        \
        const float tt = fmaf(m, v.x, 1.0f);                              \
        ACC = fmaf(fabsf(rd), fast_lg2(tt), ACC);                         \
    }

#pragma unroll
    for (int k = 1; k <= 60; k += 4) {
        LL_PAIR(k,     acc0)
        LL_PAIR(k + 1, acc1)
        LL_PAIR(k + 2, acc2)
        LL_PAIR(k + 3, acc3)
    }
    LL_PAIR(61, acc0)
    LL_PAIR(62, acc1)
    LL_PAIR(63, acc2)

    // distance-64 pairs: threads j<64 (warps 0,1 — uniform), never wraps
    if (j < LL_L / 2) {
        const float2 v = T[j + 64];
        acc3 = fmaf(v.y - rS, fast_lg2(fmaf(eS, v.x, 1.0f)), acc3);
    }
#undef LL_PAIR

    float acc = (acc0 + acc1) + (acc2 + acc3);

    // block reduction (4 warps)
#pragma unroll
    for (int off = 16; off; off >>= 1)
        acc += __shfl_xor_sync(0xffffffffu, acc, off);
    if ((j & 31) == 0) wsum[j >> 5] = acc;
    __syncthreads();

    if (j == 0) {
        float s = (wsum[0] + wsum[1] + wsum[2] + wsum[3]) * LN2;
        const int n0 = hist[0], n1 = hist[1], n2 = hist[2];
        const int n3 = hist[3], n4 = hist[4];
        const int cnt = n1 * n0
                      + n2 * (n0 + n1)
                      + n3 * (n0 + n1 + n2)
                      + n4 * (n0 + n1 + n2 + n3);
        if (cnt > 0) {
            atomicAdd(&g_sum, s / (float)cnt);
            atomicAdd(&g_valid, 1);
        }
        __threadfence();
        const int prev = atomicAdd(&g_done, 1);
        if (prev == gridDim.x - 1) {
            const float gs = g_sum;
            const int   gv = g_valid;
            out[0] = (gv > 0) ? (gs / (float)gv) : 0.0f;
            g_sum   = 0.0f;
            g_valid = 0;
            g_done  = 0;
        }
    }
}

extern "C" void kernel_launch(void* const* d_in, const int* in_sizes, int n_in,
                              void* d_out, int out_size)
{
    const float* pred = (const float*)d_in[0];
    const float* rel  = (const float*)d_in[1];
    float* out = (float*)d_out;

    ll_main_kernel<<<LL_B, LL_L>>>(pred, rel, out);
}

// round 9
// speedup vs baseline: 1.4501x; 1.4501x over previous
#include <cuda_runtime.h>
#include <cstdint>

// LambdaLoss: B=4096 lists, L=128 items.
// loss = mean over valid lists of
//        [ sum_{i,j: rel_i>rel_j} (rel_i-rel_j)*softplus(-(p_i-p_j)) / cnt ]
//
// softplus(-(p_w-p_l)) = ln(1 + e^{p_l}*e^{-p_w}); precompute e_i, rec_i.
// Counting-sort by rel (ascending): winner = higher sorted index, so pair
// orientation is STATIC for almost all pair forms (no data-dependent select).
//
// R9: 4x4 tiling, one warp per list. Thread lj owns sorted items
// A=lj, B=lj+32, C=lj+64, D=lj+96 (lj in [0,32)). For k=1..15: load
// v1..v4 = S[lj+k +{0,32,64,96}] and form 16 pairs covering ring distances
// {k, 32-k, 32+k, 64-k} at every start; k=16 forms 8 pairs (d=16,48);
// the 6 intra-self pairs (d=32 x4, d=64 x2) are register-only.
// 32*(15*16+8+6) = 8128 = C(128,2). Loads: 4 B of smem per pair.
// Only v4 can ring-wrap; one ISETP per k shared by its 4 pair forms.

#define LL_B   4096
#define LL_L   128
#define LOG2E  1.4426950408889634f
#define LN2    0.6931471805599453f

__device__ float g_sum   = 0.0f;
__device__ int   g_valid = 0;
__device__ int   g_done  = 0;

__device__ __forceinline__ float fast_ex2(float x) {
    float r; asm("ex2.approx.f32 %0, %1;" : "=f"(r) : "f"(x)); return r;
}
__device__ __forceinline__ float fast_lg2(float x) {
    float r; asm("lg2.approx.f32 %0, %1;" : "=f"(r) : "f"(x)); return r;
}

__global__ __launch_bounds__(128) void ll_main_kernel(
    const float* __restrict__ pred,
    const float* __restrict__ rel,
    float* __restrict__ out)
{
    // 4 lists per block, one warp each. S: sorted (e, rec, rel, _), +16 dup.
    __shared__ float4 S[4][144];
    __shared__ int    hist[4][8];
    __shared__ int    base[4][8];

    const int t    = threadIdx.x;
    const int w    = t >> 5;              // warp = list-in-block
    const int lj   = t & 31;
    const int list = blockIdx.x * 4 + w;

    const float* P = pred + list * LL_L;
    const float* R = rel  + list * LL_L;

    float pv[4], rv[4], ev[4], cv[4];
    int   cl[4];
#pragma unroll
    for (int i = 0; i < 4; i++) {
        pv[i] = P[lj + 32 * i];
        rv[i] = R[lj + 32 * i];
        cl[i] = (int)rv[i];                // rel in {0..4}
        float q = pv[i] * LOG2E;
        ev[i] = fast_ex2(q);
        cv[i] = fast_ex2(-q);
    }

    if (lj < 8) hist[w][lj] = 0;
    __syncwarp();
#pragma unroll
    for (int i = 0; i < 4; i++) atomicAdd(&hist[w][cl[i]], 1);
    __syncwarp();
    if (lj == 0) {
        int a = 0;
#pragma unroll
        for (int c = 0; c < 5; c++) { base[w][c] = a; a += hist[w][c]; }
    }
    __syncwarp();
#pragma unroll
    for (int i = 0; i < 4; i++) {
        int pos = atomicAdd(&base[w][cl[i]], 1);
        float4 tu = make_float4(ev[i], cv[i], rv[i], 0.0f);
        S[w][pos] = tu;
        if (pos < 16) S[w][pos + 128] = tu;   // ring-wrap duplicate
    }
    __syncwarp();

    const float4* Sw = S[w];
    const float4 sa = Sw[lj];
    const float4 sb = Sw[lj + 32];
    const float4 sc = Sw[lj + 64];
    const float4 sd = Sw[lj + 96];
    const float eA = sa.x, cA = sa.y, rA = sa.z;
    const float eB = sb.x, cB = sb.y, rB = sb.z;
    const float eC = sc.x, cC = sc.y, rC = sc.z;
    const float eD = sd.x, cD = sd.y, rD = sd.z;

    float acc0 = 0.0f, acc1 = 0.0f, acc2 = 0.0f, acc3 = 0.0f;

    // partner (higher sorted index) wins: t = e_self * rec_p, rd = r_p - r_s >= 0
#define PW(V, ES, RS, ACC) \
    ACC = fmaf((V).z - (RS), fast_lg2(fmaf((ES), (V).y, 1.0f)), ACC);
    // self (higher sorted index) wins: t = e_p * rec_self, rd = r_s - r_p >= 0
#define SW(V, CS, RS, ACC) \
    ACC = fmaf((RS) - (V).z, fast_lg2(fmaf((V).x, (CS), 1.0f)), ACC);
    // dynamic (v4 may wrap): wrapped -> self wins, else partner wins
#define DYN(V, WR, ES, CS, RS, ACC)                                       \
    {                                                                     \
        float tt = (WR) ? fmaf((V).x, (CS), 1.0f)                         \
                        : fmaf((ES), (V).y, 1.0f);                        \
        ACC = fmaf(fabsf((V).z - (RS)), fast_lg2(tt), ACC);               \
    }

#pragma unroll
    for (int k = 1; k < 16; k++) {
        const float4 v1 = Sw[lj + k];
        const float4 v2 = Sw[lj + 32 + k];
        const float4 v3 = Sw[lj + 64 + k];
        const float4 v4 = Sw[lj + 96 + k];
        const bool  wr = (lj + 96 + k) >= LL_L;

        // d = k
        PW(v1, eA, rA, acc0)  PW(v2, eB, rB, acc1)  PW(v3, eC, rC, acc2)
        DYN(v4, wr, eD, cD, rD, acc3)
        // d = 32+k
        PW(v2, eA, rA, acc0)  PW(v3, eB, rB, acc1)
        DYN(v4, wr, eC, cC, rC, acc2)
        SW(v1, cD, rD, acc3)
        // d = 64-k
        PW(v3, eA, rA, acc0)
        DYN(v4, wr, eB, cB, rB, acc1)
        SW(v1, cC, rC, acc2)  SW(v2, cD, rD, acc3)
        // d = 32-k
        DYN(v4, wr, eA, cA, rA, acc0)
        SW(v1, cB, rB, acc1)  SW(v2, cC, rC, acc2)  SW(v3, cD, rD, acc3)
    }
    {   // k = 16: d=16 and d=48 only (others would duplicate)
        const float4 v1 = Sw[lj + 16];
        const float4 v2 = Sw[lj + 48];
        const float4 v3 = Sw[lj + 80];
        const float4 v4 = Sw[lj + 112];
        const bool  wr = (lj + 112) >= LL_L;
        PW(v1, eA, rA, acc0)  PW(v2, eB, rB, acc1)  PW(v3, eC, rC, acc2)
        DYN(v4, wr, eD, cD, rD, acc3)
        PW(v2, eA, rA, acc0)  PW(v3, eB, rB, acc1)
        DYN(v4, wr, eC, cC, rC, acc2)
        SW(v1, cD, rD, acc3)
    }
    // register-only pairs: d=32 (A-B, B-C, C-D, D-A) and d=64 (A-C, B-D)
    acc0 = fmaf(rB - rA, fast_lg2(fmaf(eA, cB, 1.0f)), acc0);
    acc1 = fmaf(rC - rB, fast_lg2(fmaf(eB, cC, 1.0f)), acc1);
    acc2 = fmaf(rD - rC, fast_lg2(fmaf(eC, cD, 1.0f)), acc2);
    acc3 = fmaf(rD - rA, fast_lg2(fmaf(eA, cD, 1.0f)), acc3);
    acc0 = fmaf(rC - rA, fast_lg2(fmaf(eA, cC, 1.0f)), acc0);
    acc1 = fmaf(rD - rB, fast_lg2(fmaf(eB, cD, 1.0f)), acc1);

#undef PW
#undef SW
#undef DYN

    float acc = (acc0 + acc1) + (acc2 + acc3);

    // warp reduction (one warp == one list)
#pragma unroll
    for (int off = 16; off; off >>= 1)
        acc += __shfl_xor_sync(0xffffffffu, acc, off);

    if (lj == 0) {
        float s = acc * LN2;
        const int n0 = hist[w][0], n1 = hist[w][1], n2 = hist[w][2];
        const int n3 = hist[w][3], n4 = hist[w][4];
        const int cnt = n1 * n0
                      + n2 * (n0 + n1)
                      + n3 * (n0 + n1 + n2)
                      + n4 * (n0 + n1 + n2 + n3);
        if (cnt > 0) {
            atomicAdd(&g_sum, s / (float)cnt);
            atomicAdd(&g_valid, 1);
        }
        __threadfence();
        const int prev = atomicAdd(&g_done, 1);
        if (prev == LL_B - 1) {
            const float gs = g_sum;
            const int   gv = g_valid;
            out[0] = (gv > 0) ? (gs / (float)gv) : 0.0f;
            g_sum   = 0.0f;
            g_valid = 0;
            g_done  = 0;
        }
    }
}

extern "C" void kernel_launch(void* const* d_in, const int* in_sizes, int n_in,
                              void* d_out, int out_size)
{
    const float* pred = (const float*)d_in[0];
    const float* rel  = (const float*)d_in[1];
    float* out = (float*)d_out;

    ll_main_kernel<<<LL_B / 4, 128>>>(pred, rel, out);
}

// round 10
// speedup vs baseline: 1.4853x; 1.0243x over previous
#include <cuda_runtime.h>
#include <cstdint>

// LambdaLoss: B=4096 lists, L=128 items.
// loss = mean over valid lists of
//        [ sum_{i,j: rel_i>rel_j} (rel_i-rel_j)*softplus(-(p_i-p_j)) / cnt ]
//
// softplus(-(p_w-p_l)) = ln(1 + e^{p_l}*e^{-p_w}); precompute e_i, rec_i.
// Counting-sort by rel (ascending): winner = higher sorted index -> pair
// orientation is static per pair form (no data-dependent select).
//
// R10: 4x4 tiling with TWO warps per list (k-parity split) for 2x warp
// supply vs R9. Thread lj owns sorted items A..D at lj+{0,32,64,96}.
// Per k: load v1..v4 = S[lj+k+{0,32,64,96}], form 16 pairs covering ring
// distances {k, 32-k, 32+k, 64-k}. Warp0: odd k (1..15) + 6 register-only
// pairs (d=32,64). Warp1: even k (2..14) + k=16 (8 pairs, d=16/48).
// Per list: 32*(8*16+6 + 7*16+8) = 8128 = C(128,2). Only v4 can wrap.

#define LL_B   4096
#define LL_L   128
#define LOG2E  1.4426950408889634f
#define LN2    0.6931471805599453f

__device__ float g_sum   = 0.0f;
__device__ int   g_valid = 0;
__device__ int   g_done  = 0;

__device__ __forceinline__ float fast_ex2(float x) {
    float r; asm("ex2.approx.f32 %0, %1;" : "=f"(r) : "f"(x)); return r;
}
__device__ __forceinline__ float fast_lg2(float x) {
    float r; asm("lg2.approx.f32 %0, %1;" : "=f"(r) : "f"(x)); return r;
}

__global__ __launch_bounds__(128) void ll_main_kernel(
    const float* __restrict__ pred,
    const float* __restrict__ rel,
    float* __restrict__ out)
{
    // 2 lists per block, 2 warps each. S: sorted (e, rec, rel, _), +16 dup.
    __shared__ float4 S[2][144];
    __shared__ int    hist[2][8];
    __shared__ int    base[2][8];
    __shared__ float  wsum[4];

    const int t    = threadIdx.x;
    const int half = t >> 6;              // which list in this block
    const int t64  = t & 63;              // thread within the list's 2 warps
    const int wl   = (t >> 5) & 1;        // warp-in-list: 0 or 1
    const int lj   = t & 31;
    const int list = blockIdx.x * 2 + half;

    const float* P = pred + list * LL_L;
    const float* R = rel  + list * LL_L;

    // prologue: 64 threads per list handle 2 items each
    const float p0 = P[t64],       r0 = R[t64];
    const float p1 = P[t64 + 64],  r1 = R[t64 + 64];
    const int   c0 = (int)r0, c1 = (int)r1;     // rel in {0..4}
    const float q0 = p0 * LOG2E,  q1 = p1 * LOG2E;
    const float e0 = fast_ex2(q0), rc0 = fast_ex2(-q0);
    const float e1 = fast_ex2(q1), rc1 = fast_ex2(-q1);

    if (t64 < 8) hist[half][t64] = 0;
    __syncthreads();
    atomicAdd(&hist[half][c0], 1);
    atomicAdd(&hist[half][c1], 1);
    __syncthreads();
    if (t64 == 0) {
        int a = 0;
#pragma unroll
        for (int c = 0; c < 5; c++) { base[half][c] = a; a += hist[half][c]; }
    }
    __syncthreads();
    {
        const int pos0 = atomicAdd(&base[half][c0], 1);
        const int pos1 = atomicAdd(&base[half][c1], 1);
        const float4 u0 = make_float4(e0, rc0, r0, 0.0f);
        const float4 u1 = make_float4(e1, rc1, r1, 0.0f);
        S[half][pos0] = u0;
        S[half][pos1] = u1;
        if (pos0 < 16) S[half][pos0 + 128] = u0;
        if (pos1 < 16) S[half][pos1 + 128] = u1;
    }
    __syncthreads();

    const float4* Sw = S[half];
    const float4 sa = Sw[lj];
    const float4 sb = Sw[lj + 32];
    const float4 sc = Sw[lj + 64];
    const float4 sd = Sw[lj + 96];
    const float eA = sa.x, cA = sa.y, rA = sa.z;
    const float eB = sb.x, cB = sb.y, rB = sb.z;
    const float eC = sc.x, cC = sc.y, rC = sc.z;
    const float eD = sd.x, cD = sd.y, rD = sd.z;

    float acc0 = 0.0f, acc1 = 0.0f, acc2 = 0.0f, acc3 = 0.0f;

    // partner (higher sorted index) wins: t = e_self*rec_p, rd = r_p - r_s >= 0
#define PW(V, ES, RS, ACC) \
    ACC = fmaf((V).z - (RS), fast_lg2(fmaf((ES), (V).y, 1.0f)), ACC);
    // self (higher sorted index) wins: t = e_p*rec_self, rd = r_s - r_p >= 0
#define SW(V, CS, RS, ACC) \
    ACC = fmaf((RS) - (V).z, fast_lg2(fmaf((V).x, (CS), 1.0f)), ACC);
    // dynamic (v4 may wrap): wrapped -> self wins, else partner wins
#define DYN(V, WR, ES, CS, RS, ACC)                                       \
    {                                                                     \
        float tt = (WR) ? fmaf((V).x, (CS), 1.0f)                         \
                        : fmaf((ES), (V).y, 1.0f);                        \
        ACC = fmaf(fabsf((V).z - (RS)), fast_lg2(tt), ACC);               \
    }

    // warp0: k = 1,3,...,15   warp1: k = 2,4,...,14 (k=16 tail below)
#pragma unroll
    for (int kk = 0; kk < 7; kk++) {
        const int k = 1 + wl + 2 * kk;
        const float4 v1 = Sw[lj + k];
        const float4 v2 = Sw[lj + 32 + k];
        const float4 v3 = Sw[lj + 64 + k];
        const float4 v4 = Sw[lj + 96 + k];
        const bool  wr = (lj + 96 + k) >= LL_L;

        // d = k
        PW(v1, eA, rA, acc0)  PW(v2, eB, rB, acc1)  PW(v3, eC, rC, acc2)
        DYN(v4, wr, eD, cD, rD, acc3)
        // d = 32+k
        PW(v2, eA, rA, acc0)  PW(v3, eB, rB, acc1)
        DYN(v4, wr, eC, cC, rC, acc2)
        SW(v1, cD, rD, acc3)
        // d = 64-k
        PW(v3, eA, rA, acc0)
        DYN(v4, wr, eB, cB, rB, acc1)
        SW(v1, cC, rC, acc2)  SW(v2, cD, rD, acc3)
        // d = 32-k
        DYN(v4, wr, eA, cA, rA, acc0)
        SW(v1, cB, rB, acc1)  SW(v2, cC, rC, acc2)  SW(v3, cD, rD, acc3)
    }

    if (wl == 0) {
        // k = 15 (last odd)
        const int k = 15;
        const float4 v1 = Sw[lj + k];
        const float4 v2 = Sw[lj + 32 + k];
        const float4 v3 = Sw[lj + 64 + k];
        const float4 v4 = Sw[lj + 96 + k];
        const bool  wr = (lj + 96 + k) >= LL_L;
        PW(v1, eA, rA, acc0)  PW(v2, eB, rB, acc1)  PW(v3, eC, rC, acc2)
        DYN(v4, wr, eD, cD, rD, acc3)
        PW(v2, eA, rA, acc0)  PW(v3, eB, rB, acc1)
        DYN(v4, wr, eC, cC, rC, acc2)
        SW(v1, cD, rD, acc3)
        PW(v3, eA, rA, acc0)
        DYN(v4, wr, eB, cB, rB, acc1)
        SW(v1, cC, rC, acc2)  SW(v2, cD, rD, acc3)
        DYN(v4, wr, eA, cA, rA, acc0)
        SW(v1, cB, rB, acc1)  SW(v2, cC, rC, acc2)  SW(v3, cD, rD, acc3)

        // register-only pairs: d=32 (A-B,B-C,C-D,D-A) and d=64 (A-C,B-D)
        acc0 = fmaf(rB - rA, fast_lg2(fmaf(eA, cB, 1.0f)), acc0);
        acc1 = fmaf(rC - rB, fast_lg2(fmaf(eB, cC, 1.0f)), acc1);
        acc2 = fmaf(rD - rC, fast_lg2(fmaf(eC, cD, 1.0f)), acc2);
        acc3 = fmaf(rD - rA, fast_lg2(fmaf(eA, cD, 1.0f)), acc3);
        acc0 = fmaf(rC - rA, fast_lg2(fmaf(eA, cC, 1.0f)), acc0);
        acc1 = fmaf(rD - rB, fast_lg2(fmaf(eB, cD, 1.0f)), acc1);
    } else {
        // k = 16: d=16 and d=48 only (other forms would duplicate)
        const float4 v1 = Sw[lj + 16];
        const float4 v2 = Sw[lj + 48];
        const float4 v3 = Sw[lj + 80];
        const float4 v4 = Sw[lj + 112];
        const bool  wr = (lj + 112) >= LL_L;
        PW(v1, eA, rA, acc0)  PW(v2, eB, rB, acc1)  PW(v3, eC, rC, acc2)
        DYN(v4, wr, eD, cD, rD, acc3)
        PW(v2, eA, rA, acc0)  PW(v3, eB, rB, acc1)
        DYN(v4, wr, eC, cC, rC, acc2)
        SW(v1, cD, rD, acc3)
    }

#undef PW
#undef SW
#undef DYN

    float acc = (acc0 + acc1) + (acc2 + acc3);

    // warp reduction, then combine the list's two warps
#pragma unroll
    for (int off = 16; off; off >>= 1)
        acc += __shfl_xor_sync(0xffffffffu, acc, off);
    if (lj == 0) wsum[t >> 5] = acc;
    __syncthreads();

    if (t64 == 0) {
        float s = (wsum[half * 2] + wsum[half * 2 + 1]) * LN2;
        const int n0 = hist[half][0], n1 = hist[half][1], n2 = hist[half][2];
        const int n3 = hist[half][3], n4 = hist[half][4];
        const int cnt = n1 * n0
                      + n2 * (n0 + n1)
                      + n3 * (n0 + n1 + n2)
                      + n4 * (n0 + n1 + n2 + n3);
        if (cnt > 0) {
            atomicAdd(&g_sum, s / (float)cnt);
            atomicAdd(&g_valid, 1);
        }
        __threadfence();
        const int prev = atomicAdd(&g_done, 1);
        if (prev == LL_B - 1) {
            const float gs = g_sum;
            const int   gv = g_valid;
            out[0] = (gv > 0) ? (gs / (float)gv) : 0.0f;
            g_sum   = 0.0f;
            g_valid = 0;
            g_done  = 0;
        }
    }
}

extern "C" void kernel_launch(void* const* d_in, const int* in_sizes, int n_in,
                              void* d_out, int out_size)
{
    const float* pred = (const float*)d_in[0];
    const float* rel  = (const float*)d_in[1];
    float* out = (float*)d_out;

    ll_main_kernel<<<LL_B / 2, 128>>>(pred, rel, out);
}